// round 15
// baseline (speedup 1.0000x reference)
#include <cuda_runtime.h>
#include <cuda_fp16.h>
#include <math.h>

#define Bdim 2
#define Hdim 16
#define Sdim 2048
#define Ddim 64

constexpr int TQ = 64;
constexpr int TK = 128;
constexpr int NT = Sdim / TK;   // 16

constexpr int OFF_Q  = 0;       // 64 x 128B = 8KB
constexpr int OFF_K0 = 8192;    // 128 x 128B = 16KB
constexpr int OFF_K1 = 24576;
constexpr int OFF_V  = 40960;   // 16KB (doubles as s-exchange between passes)
constexpr int SMEM_BYTES = 57344;   // 56KB -> 4 CTAs/SM

// ---- scratch (device globals; no allocation) ----
__device__ __half g_qh[(size_t)Bdim*Hdim*Sdim*Ddim];
__device__ __half g_kh[(size_t)Bdim*Hdim*Sdim*Ddim];
__device__ __half g_vh[(size_t)Bdim*Hdim*Sdim*Ddim];
__device__ unsigned g_mb[(size_t)Bdim*Sdim*Sdim/32];

__device__ __forceinline__ unsigned smaddr(const void* p) {
    return (unsigned)__cvta_generic_to_shared(p);
}
__device__ __forceinline__ unsigned sw128(unsigned off) {
    return off ^ ((off >> 3) & 0x70);
}
__device__ __forceinline__ void ldsm_x4(unsigned a, unsigned &r0, unsigned &r1, unsigned &r2, unsigned &r3) {
    asm volatile("ldmatrix.sync.aligned.m8n8.x4.shared.b16 {%0,%1,%2,%3}, [%4];"
                 : "=r"(r0), "=r"(r1), "=r"(r2), "=r"(r3) : "r"(a));
}
__device__ __forceinline__ void ldsm_x4_t(unsigned a, unsigned &r0, unsigned &r1, unsigned &r2, unsigned &r3) {
    asm volatile("ldmatrix.sync.aligned.m8n8.x4.trans.shared.b16 {%0,%1,%2,%3}, [%4];"
                 : "=r"(r0), "=r"(r1), "=r"(r2), "=r"(r3) : "r"(a));
}
__device__ __forceinline__ void mma16816(float* c, const unsigned* a, unsigned b0, unsigned b1) {
    asm volatile("mma.sync.aligned.m16n8k16.row.col.f32.f16.f16.f32 "
                 "{%0,%1,%2,%3}, {%4,%5,%6,%7}, {%8,%9}, {%0,%1,%2,%3};"
                 : "+f"(c[0]), "+f"(c[1]), "+f"(c[2]), "+f"(c[3])
                 : "r"(a[0]), "r"(a[1]), "r"(a[2]), "r"(a[3]), "r"(b0), "r"(b1));
}
__device__ __forceinline__ unsigned pack_h2(float x, float y) {
    __half2 h = __floats2half2_rn(x, y);
    return *(unsigned*)&h;
}
__device__ __forceinline__ float ex2(float x) {
    float r; asm("ex2.approx.f32 %0, %1;" : "=f"(r) : "f"(x)); return r;
}
__device__ __forceinline__ void cp16u(unsigned dst, const __half* src) {
    asm volatile("cp.async.cg.shared.global [%0], [%1], 16;" :: "r"(dst), "l"(src));
}
#define CP_COMMIT asm volatile("cp.async.commit_group;")
#define CP_WAIT0  asm volatile("cp.async.wait_group 0;")
#define CP_WAIT1  asm volatile("cp.async.wait_group 1;")

__device__ __forceinline__ void ld_tile128(unsigned dst, const __half* src, int rowbase, int t) {
    const int r0 = t >> 3, cc = t & 7;
    #pragma unroll
    for (int i = 0; i < 8; ++i) {
        int row = r0 + 16*i;
        cp16u(dst + sw128(row*128 + cc*16), src + (size_t)(rowbase+row)*Ddim + cc*8);
    }
}

// ================= fused prep kernel =================
__global__ void __launch_bounds__(256) prep_all(const float* __restrict__ q,
                                                const float* __restrict__ k,
                                                const float* __restrict__ v,
                                                const float* __restrict__ mask) {
    const int blk = blockIdx.x;
    if (blk < 2048) {
        const float qs = 0.18033688011112042f;   // 0.125 * log2(e)
        size_t i = ((size_t)blk*256 + threadIdx.x)*8;
        #pragma unroll
        for (int j = 0; j < 2; ++j) {
            size_t ii = i + j*4;
            float4 a = *(const float4*)(q+ii);
            float4 b = *(const float4*)(k+ii);
            float4 c = *(const float4*)(v+ii);
            __half2* dq = (__half2*)(g_qh+ii);
            __half2* dk = (__half2*)(g_kh+ii);
            __half2* dv = (__half2*)(g_vh+ii);
            dq[0]=__floats2half2_rn(a.x*qs,a.y*qs); dq[1]=__floats2half2_rn(a.z*qs,a.w*qs);
            dk[0]=__floats2half2_rn(b.x,b.y);       dk[1]=__floats2half2_rn(b.z,b.w);
            dv[0]=__floats2half2_rn(c.x,c.y);       dv[1]=__floats2half2_rn(c.z,c.w);
        }
    } else {
        int W    = (blk - 2048)*8 + (threadIdx.x >> 5);
        int lane = threadIdx.x & 31;
        #pragma unroll
        for (int j = 0; j < 4; ++j) {
            int gw = W*4 + j;
            float4 f = ((const float4*)mask)[(size_t)gw*32 + lane];
            unsigned b0 = __ballot_sync(0xffffffffu, f.x != 0.f);
            unsigned b1 = __ballot_sync(0xffffffffu, f.y != 0.f);
            unsigned b2 = __ballot_sync(0xffffffffu, f.z != 0.f);
            unsigned b3 = __ballot_sync(0xffffffffu, f.w != 0.f);
            if (lane == 0)
                *(uint4*)(g_mb + (size_t)gw*4) = make_uint4(b0, b1, b2, b3);
        }
    }
}

// ================= main kernel: 4 CTAs/SM =================
__global__ void __launch_bounds__(128, 4) attn_mma_kernel(
    float* __restrict__ out, float* __restrict__ wgt)
{
    extern __shared__ __align__(1024) char smraw[];
    const unsigned sb = smaddr(smraw);

    const int t    = threadIdx.x;
    const int lane = t & 31;
    const int w    = t >> 5;
    const int bh   = blockIdx.x >> 5;
    const int qt   = blockIdx.x & 31;
    const int b    = bh >> 4;
    const int qbase = qt * TQ;

    const __half* qp = g_qh + (size_t)bh * Sdim * Ddim;
    const __half* kp = g_kh + (size_t)bh * Sdim * Ddim;
    const __half* vp = g_vh + (size_t)bh * Sdim * Ddim;
    float* wp = wgt + (size_t)bh * Sdim * Sdim;
    float* op = out + (size_t)bh * Sdim * Ddim;

    // ---- Q tile (64 rows) + K[0] ----
    {
        const int r0 = t >> 3, cc = t & 7;
        #pragma unroll
        for (int i = 0; i < 4; ++i) {
            int row = r0 + 16*i;
            cp16u(sb + OFF_Q + sw128(row*128 + cc*16), qp + (size_t)(qbase+row)*Ddim + cc*8);
        }
    }
    ld_tile128(sb + OFF_K0, kp, 0, t);
    CP_COMMIT; CP_WAIT0;
    __syncthreads();

    const int qr  = lane >> 2;
    const int qc  = (lane & 3) * 2;
    const int wsel = qc & 3;
    const int bsh  = qc >> 2;

    // ====== PASS A: warp (g,h) = (q-block of 32 rows, k-half of 64 cols) ======
    const int g = w >> 1;
    const int h = w & 1;
    const int h64 = h * 64;

    unsigned qa2[2][4][4];
    #pragma unroll
    for (int j = 0; j < 2; ++j)
        #pragma unroll
        for (int ks = 0; ks < 4; ++ks) {
            unsigned a = sb + OFF_Q + sw128((g*32 + j*16 + (lane & 15))*128
                                            + (ks*16 + (lane >> 4)*8)*2);
            ldsm_x4(a, qa2[j][ks][0], qa2[j][ks][1], qa2[j][ks][2], qa2[j][ks][3]);
        }

    const unsigned* mrA[4];
    #pragma unroll
    for (int j = 0; j < 2; ++j) {
        mrA[2*j]   = g_mb + ((size_t)b*Sdim + qbase + g*32 + j*16 + qr)    *(Sdim/32);
        mrA[2*j+1] = g_mb + ((size_t)b*Sdim + qbase + g*32 + j*16 + qr + 8)*(Sdim/32);
    }

    float s[4] = {0.f, 0.f, 0.f, 0.f};

    for (int kt = 0; kt < NT; ++kt) {
        unsigned kc = sb + ((kt & 1) ? OFF_K1 : OFF_K0);
        if (kt+1 < NT) ld_tile128(sb + ((kt & 1) ? OFF_K0 : OFF_K1), kp, (kt+1)*TK, t);
        CP_COMMIT;

        float sf[2][8][4];
        #pragma unroll
        for (int j = 0; j < 2; ++j)
            #pragma unroll
            for (int nt = 0; nt < 8; ++nt) {
                sf[j][nt][0]=0.f; sf[j][nt][1]=0.f; sf[j][nt][2]=0.f; sf[j][nt][3]=0.f;
            }

        #pragma unroll
        for (int ks = 0; ks < 4; ++ks) {
            #pragma unroll
            for (int nt2 = 0; nt2 < 4; ++nt2) {
                unsigned b0,b1,b2,b3;
                unsigned a = kc + sw128((h64 + nt2*16 + (lane & 7) + ((lane >> 4) << 3))*128
                                        + (ks*16 + ((lane >> 3) & 1)*8)*2);
                ldsm_x4(a, b0, b1, b2, b3);
                // K fragments reused across both q-subtiles (halves ldsm traffic)
                mma16816(sf[0][2*nt2],   qa2[0][ks], b0, b1);
                mma16816(sf[0][2*nt2+1], qa2[0][ks], b2, b3);
                mma16816(sf[1][2*nt2],   qa2[1][ks], b0, b1);
                mma16816(sf[1][2*nt2+1], qa2[1][ks], b2, b3);
            }
        }

        #pragma unroll
        for (int j = 0; j < 2; ++j) {
            uint4 mwa = *(const uint4*)(mrA[2*j]   + kt*4);
            uint4 mwb = *(const uint4*)(mrA[2*j+1] + kt*4);
            const unsigned* wa = (const unsigned*)&mwa;
            const unsigned* wb = (const unsigned*)&mwb;
            const int sh = bsh + h*16;
            unsigned a0 = wa[wsel]   >> sh;
            unsigned a1 = wa[wsel+1] >> sh;
            unsigned c0 = wb[wsel]   >> sh;
            unsigned c1 = wb[wsel+1] >> sh;
            #pragma unroll
            for (int nt = 0; nt < 8; ++nt) {
                s[2*j]   += (((a0 >> (nt*2)) & 1) ? 0.f : ex2(sf[j][nt][0]))
                          + (((a1 >> (nt*2)) & 1) ? 0.f : ex2(sf[j][nt][1]));
                s[2*j+1] += (((c0 >> (nt*2)) & 1) ? 0.f : ex2(sf[j][nt][2]))
                          + (((c1 >> (nt*2)) & 1) ? 0.f : ex2(sf[j][nt][3]));
            }
        }

        CP_WAIT0;
        __syncthreads();
    }

    // ---- s combine via V smem region (free until pass B V loads) ----
    #pragma unroll
    for (int i = 0; i < 4; ++i) {
        s[i] += __shfl_xor_sync(0xffffffffu, s[i], 1);
        s[i] += __shfl_xor_sync(0xffffffffu, s[i], 2);
    }
    float* SS = (float*)(smraw + OFF_V);      // [2 k-halves][64 rows]
    if ((lane & 3) == 0) {
        float* sp = SS + h*64 + g*32;
        sp[qr]      = s[0];
        sp[qr + 8]  = s[1];
        sp[qr + 16] = s[2];
        sp[qr + 24] = s[3];
    }
    __syncthreads();
    const int rl0 = w*16 + qr;                // pass-B local rows
    const int rl1 = rl0 + 8;
    const float inv0 = 1.f / (SS[rl0] + SS[64 + rl0]);
    const float inv1 = 1.f / (SS[rl1] + SS[64 + rl1]);
    __syncthreads();                          // everyone read SS before V overwrites

    const int row0 = qbase + rl0;
    const int row1 = qbase + rl1;
    const unsigned* mb0 = g_mb + ((size_t)b*Sdim + row0)*(Sdim/32);
    const unsigned* mb1 = g_mb + ((size_t)b*Sdim + row1)*(Sdim/32);

    // pass-B Q fragments (rows w*16..+16)
    unsigned qa[4][4];
    #pragma unroll
    for (int ks = 0; ks < 4; ++ks) {
        unsigned a = sb + OFF_Q + sw128((w*16 + (lane & 15))*128 + (ks*16 + (lane >> 4)*8)*2);
        ldsm_x4(a, qa[ks][0], qa[ks][1], qa[ks][2], qa[ks][3]);
    }

    // ================= PASS B: N-halved, improved pipelining =================
    float of[8][4];
    #pragma unroll
    for (int nt = 0; nt < 8; ++nt) { of[nt][0]=0.f; of[nt][1]=0.f; of[nt][2]=0.f; of[nt][3]=0.f; }

    ld_tile128(sb + OFF_V,  vp, 0, t);        // group: V(0)
    CP_COMMIT;
    ld_tile128(sb + OFF_K0, kp, 0, t);        // group: K(0)
    CP_COMMIT; CP_WAIT0;
    __syncthreads();

    for (int kt = 0; kt < NT; ++kt) {
        const int kbase = kt * TK;
        unsigned kc = sb + ((kt & 1) ? OFF_K1 : OFF_K0);
        if (kt+1 < NT) { ld_tile128(sb + ((kt & 1) ? OFF_K0 : OFF_K1), kp, (kt+1)*TK, t); }
        CP_COMMIT;                             // group: K(kt+1)  (empty group on last iter)

        uint4 mwa = *(const uint4*)(mb0 + kt*4);
        uint4 mwb = *(const uint4*)(mb1 + kt*4);
        const unsigned* wa = (const unsigned*)&mwa;
        const unsigned* wb = (const unsigned*)&mwb;

        #pragma unroll
        for (int h2 = 0; h2 < 2; ++h2) {
            float sf[8][4];
            #pragma unroll
            for (int nt = 0; nt < 8; ++nt) { sf[nt][0]=0.f; sf[nt][1]=0.f; sf[nt][2]=0.f; sf[nt][3]=0.f; }

            #pragma unroll
            for (int ks = 0; ks < 4; ++ks) {
                #pragma unroll
                for (int nt2 = 0; nt2 < 4; ++nt2) {
                    unsigned b0,b1,b2,b3;
                    unsigned a = kc + sw128((h2*64 + nt2*16 + (lane & 7) + ((lane >> 4) << 3))*128
                                            + (ks*16 + ((lane >> 3) & 1)*8)*2);
                    ldsm_x4(a, b0, b1, b2, b3);
                    mma16816(sf[2*nt2],   qa[ks], b0, b1);
                    mma16816(sf[2*nt2+1], qa[ks], b2, b3);
                }
            }

            const int sh = bsh + h2*16;
            unsigned a0 = wa[wsel]   >> sh;
            unsigned a1 = wa[wsel+1] >> sh;
            unsigned c0 = wb[wsel]   >> sh;
            unsigned c1 = wb[wsel+1] >> sh;

            #pragma unroll
            for (int nt = 0; nt < 8; ++nt) {
                int col = kbase + h2*64 + nt*8 + qc;
                float w0 = ((a0 >> (nt*2)) & 1) ? 0.f : ex2(sf[nt][0]) * inv0;
                float w1 = ((a1 >> (nt*2)) & 1) ? 0.f : ex2(sf[nt][1]) * inv0;
                float w2 = ((c0 >> (nt*2)) & 1) ? 0.f : ex2(sf[nt][2]) * inv1;
                float w3 = ((c1 >> (nt*2)) & 1) ? 0.f : ex2(sf[nt][3]) * inv1;
                *(float2*)(wp + (size_t)row0*Sdim + col) = make_float2(w0, w1);
                *(float2*)(wp + (size_t)row1*Sdim + col) = make_float2(w2, w3);
                sf[nt][0]=w0; sf[nt][1]=w1; sf[nt][2]=w2; sf[nt][3]=w3;
            }

            unsigned pa[4][4];
            #pragma unroll
            for (int ks = 0; ks < 4; ++ks) {
                pa[ks][0] = pack_h2(sf[2*ks][0],   sf[2*ks][1]);
                pa[ks][1] = pack_h2(sf[2*ks][2],   sf[2*ks][3]);
                pa[ks][2] = pack_h2(sf[2*ks+1][0], sf[2*ks+1][1]);
                pa[ks][3] = pack_h2(sf[2*ks+1][2], sf[2*ks+1][3]);
            }

            if (h2 == 0) {
                CP_WAIT1;       // wait V(kt) only; K(kt+1) stays in flight
                __syncthreads();
            }

            #pragma unroll
            for (int ks = 0; ks < 4; ++ks) {
                #pragma unroll
                for (int nt2 = 0; nt2 < 4; ++nt2) {
                    unsigned b0,b1,b2,b3;
                    unsigned a = sb + OFF_V + sw128((h2*64 + ks*16 + (lane & 7) + ((lane >> 3) & 1)*8)*128
                                                    + (nt2*16 + (lane >> 4)*8)*2);
                    ldsm_x4_t(a, b0, b1, b2, b3);
                    mma16816(of[2*nt2],   pa[ks], b0, b1);
                    mma16816(of[2*nt2+1], pa[ks], b2, b3);
                }
            }
        }

        CP_WAIT0;               // K(kt+1) complete before next QK
        __syncthreads();
        if (kt+1 < NT) { ld_tile128(sb + OFF_V, vp, (kt+1)*TK, t); CP_COMMIT; }   // group: V(kt+1)
    }

    #pragma unroll
    for (int nt = 0; nt < 8; ++nt) {
        int col = nt*8 + qc;
        *(float2*)(op + (size_t)row0*Ddim + col) = make_float2(of[nt][0], of[nt][1]);
        *(float2*)(op + (size_t)row1*Ddim + col) = make_float2(of[nt][2], of[nt][3]);
    }
}

extern "C" void kernel_launch(void* const* d_in, const int* in_sizes, int n_in,
                              void* d_out, int out_size) {
    const float* q    = (const float*)d_in[0];
    const float* k    = (const float*)d_in[1];
    const float* v    = (const float*)d_in[2];
    const float* mask = (const float*)d_in[3];
    float* out = (float*)d_out;
    float* wgt = out + (size_t)Bdim*Hdim*Sdim*Ddim;

    prep_all<<<4096, 256>>>(q, k, v, mask);

    cudaFuncSetAttribute(attn_mma_kernel,
                         cudaFuncAttributeMaxDynamicSharedMemorySize, SMEM_BYTES);
    dim3 grid(Bdim*Hdim*(Sdim/TQ));
    attn_mma_kernel<<<grid, 128, SMEM_BYTES>>>(out, wgt);
}

// round 16
// speedup vs baseline: 1.0264x; 1.0264x over previous
#include <cuda_runtime.h>
#include <cuda_fp16.h>
#include <math.h>

#define Bdim 2
#define Hdim 16
#define Sdim 2048
#define Ddim 64

constexpr int TQ = 64;
constexpr int TK = 128;
constexpr int NT = Sdim / TK;   // 16

constexpr int OFF_Q  = 0;       // 64 x 128B = 8KB
constexpr int OFF_K0 = 8192;    // 128 x 128B = 16KB
constexpr int OFF_K1 = 24576;
constexpr int OFF_V  = 40960;   // 16KB
constexpr int SMEM_BYTES = 57344;   // 56KB -> 4 CTAs/SM

// ---- scratch (device globals; no allocation) ----
__device__ __half g_qh[(size_t)Bdim*Hdim*Sdim*Ddim];
__device__ __half g_kh[(size_t)Bdim*Hdim*Sdim*Ddim];
__device__ __half g_vh[(size_t)Bdim*Hdim*Sdim*Ddim];
__device__ unsigned g_mb[(size_t)Bdim*Sdim*Sdim/32];

__device__ __forceinline__ unsigned smaddr(const void* p) {
    return (unsigned)__cvta_generic_to_shared(p);
}
__device__ __forceinline__ unsigned sw128(unsigned off) {
    return off ^ ((off >> 3) & 0x70);
}
__device__ __forceinline__ void ldsm_x4(unsigned a, unsigned &r0, unsigned &r1, unsigned &r2, unsigned &r3) {
    asm volatile("ldmatrix.sync.aligned.m8n8.x4.shared.b16 {%0,%1,%2,%3}, [%4];"
                 : "=r"(r0), "=r"(r1), "=r"(r2), "=r"(r3) : "r"(a));
}
__device__ __forceinline__ void ldsm_x4_t(unsigned a, unsigned &r0, unsigned &r1, unsigned &r2, unsigned &r3) {
    asm volatile("ldmatrix.sync.aligned.m8n8.x4.trans.shared.b16 {%0,%1,%2,%3}, [%4];"
                 : "=r"(r0), "=r"(r1), "=r"(r2), "=r"(r3) : "r"(a));
}
__device__ __forceinline__ void mma16816(float* c, const unsigned* a, unsigned b0, unsigned b1) {
    asm volatile("mma.sync.aligned.m16n8k16.row.col.f32.f16.f16.f32 "
                 "{%0,%1,%2,%3}, {%4,%5,%6,%7}, {%8,%9}, {%0,%1,%2,%3};"
                 : "+f"(c[0]), "+f"(c[1]), "+f"(c[2]), "+f"(c[3])
                 : "r"(a[0]), "r"(a[1]), "r"(a[2]), "r"(a[3]), "r"(b0), "r"(b1));
}
__device__ __forceinline__ unsigned pack_h2(float x, float y) {
    __half2 h = __floats2half2_rn(x, y);
    return *(unsigned*)&h;
}
__device__ __forceinline__ float ex2(float x) {
    float r; asm("ex2.approx.f32 %0, %1;" : "=f"(r) : "f"(x)); return r;
}
__device__ __forceinline__ void cp16u(unsigned dst, const __half* src) {
    asm volatile("cp.async.cg.shared.global [%0], [%1], 16;" :: "r"(dst), "l"(src));
}
#define CP_COMMIT asm volatile("cp.async.commit_group;")
#define CP_WAIT0  asm volatile("cp.async.wait_group 0;")
#define CP_WAIT1  asm volatile("cp.async.wait_group 1;")

__device__ __forceinline__ void ld_tile128(unsigned dst, const __half* src, int rowbase, int t) {
    const int r0 = t >> 3, cc = t & 7;
    #pragma unroll
    for (int i = 0; i < 8; ++i) {
        int row = r0 + 16*i;
        cp16u(dst + sw128(row*128 + cc*16), src + (size_t)(rowbase+row)*Ddim + cc*8);
    }
}

// ================= fused prep kernel =================
__global__ void __launch_bounds__(256) prep_all(const float* __restrict__ q,
                                                const float* __restrict__ k,
                                                const float* __restrict__ v,
                                                const float* __restrict__ mask) {
    const int blk = blockIdx.x;
    if (blk < 2048) {
        const float qs = 0.18033688011112042f;   // 0.125 * log2(e)
        size_t i = ((size_t)blk*256 + threadIdx.x)*8;
        #pragma unroll
        for (int j = 0; j < 2; ++j) {
            size_t ii = i + j*4;
            float4 a = *(const float4*)(q+ii);
            float4 b = *(const float4*)(k+ii);
            float4 c = *(const float4*)(v+ii);
            __half2* dq = (__half2*)(g_qh+ii);
            __half2* dk = (__half2*)(g_kh+ii);
            __half2* dv = (__half2*)(g_vh+ii);
            dq[0]=__floats2half2_rn(a.x*qs,a.y*qs); dq[1]=__floats2half2_rn(a.z*qs,a.w*qs);
            dk[0]=__floats2half2_rn(b.x,b.y);       dk[1]=__floats2half2_rn(b.z,b.w);
            dv[0]=__floats2half2_rn(c.x,c.y);       dv[1]=__floats2half2_rn(c.z,c.w);
        }
    } else {
        int W    = (blk - 2048)*8 + (threadIdx.x >> 5);
        int lane = threadIdx.x & 31;
        #pragma unroll
        for (int j = 0; j < 4; ++j) {
            int gw = W*4 + j;
            float4 f = ((const float4*)mask)[(size_t)gw*32 + lane];
            unsigned b0 = __ballot_sync(0xffffffffu, f.x != 0.f);
            unsigned b1 = __ballot_sync(0xffffffffu, f.y != 0.f);
            unsigned b2 = __ballot_sync(0xffffffffu, f.z != 0.f);
            unsigned b3 = __ballot_sync(0xffffffffu, f.w != 0.f);
            if (lane == 0)
                *(uint4*)(g_mb + (size_t)gw*4) = make_uint4(b0, b1, b2, b3);
        }
    }
}

// ================= main kernel: 4 CTAs/SM =================
__global__ void __launch_bounds__(128, 4) attn_mma_kernel(
    float* __restrict__ out, float* __restrict__ wgt)
{
    extern __shared__ __align__(1024) char smraw[];
    const unsigned sb = smaddr(smraw);

    const int t    = threadIdx.x;
    const int lane = t & 31;
    const int w    = t >> 5;
    const int bh   = blockIdx.x >> 5;
    const int qt   = blockIdx.x & 31;
    const int b    = bh >> 4;
    const int qbase = qt * TQ;

    const __half* qp = g_qh + (size_t)bh * Sdim * Ddim;
    const __half* kp = g_kh + (size_t)bh * Sdim * Ddim;
    const __half* vp = g_vh + (size_t)bh * Sdim * Ddim;
    float* wp = wgt + (size_t)bh * Sdim * Sdim;
    float* op = out + (size_t)bh * Sdim * Ddim;

    // ---- Q tile (64 rows) + K[0] ----
    {
        const int r0 = t >> 3, cc = t & 7;
        #pragma unroll
        for (int i = 0; i < 4; ++i) {
            int row = r0 + 16*i;
            cp16u(sb + OFF_Q + sw128(row*128 + cc*16), qp + (size_t)(qbase+row)*Ddim + cc*8);
        }
    }
    ld_tile128(sb + OFF_K0, kp, 0, t);
    CP_COMMIT; CP_WAIT0;
    __syncthreads();

    unsigned qa[4][4];
    #pragma unroll
    for (int ks = 0; ks < 4; ++ks) {
        unsigned a = sb + OFF_Q + sw128((w*16 + (lane & 15))*128 + (ks*16 + (lane >> 4)*8)*2);
        ldsm_x4(a, qa[ks][0], qa[ks][1], qa[ks][2], qa[ks][3]);
    }

    const int qr  = lane >> 2;
    const int qc  = (lane & 3) * 2;
    const int row0 = qbase + w*16 + qr;
    const int row1 = row0 + 8;
    const unsigned* mb0 = g_mb + ((size_t)b*Sdim + row0)*(Sdim/32);
    const unsigned* mb1 = g_mb + ((size_t)b*Sdim + row1)*(Sdim/32);
    const int wsel = qc & 3;
    const int bsh  = qc >> 2;

    float s0 = 0.f, s1 = 0.f;

    // ================= PASS A: s only (max-free) — R14 structure =================
    for (int kt = 0; kt < NT; ++kt) {
        unsigned kc = sb + ((kt & 1) ? OFF_K1 : OFF_K0);
        if (kt+1 < NT) ld_tile128(sb + ((kt & 1) ? OFF_K0 : OFF_K1), kp, (kt+1)*TK, t);
        CP_COMMIT;

        float sf[16][4];
        #pragma unroll
        for (int nt = 0; nt < 16; ++nt) { sf[nt][0]=0.f; sf[nt][1]=0.f; sf[nt][2]=0.f; sf[nt][3]=0.f; }

        #pragma unroll
        for (int ks = 0; ks < 4; ++ks) {
            #pragma unroll
            for (int nt2 = 0; nt2 < 8; ++nt2) {
                unsigned b0,b1,b2,b3;
                unsigned a = kc + sw128((nt2*16 + (lane & 7) + ((lane >> 4) << 3))*128
                                        + (ks*16 + ((lane >> 3) & 1)*8)*2);
                ldsm_x4(a, b0, b1, b2, b3);
                mma16816(sf[2*nt2],   qa[ks], b0, b1);
                mma16816(sf[2*nt2+1], qa[ks], b2, b3);
            }
        }

        uint4 mwa = *(const uint4*)(mb0 + kt*4);
        uint4 mwb = *(const uint4*)(mb1 + kt*4);
        const unsigned* wa = (const unsigned*)&mwa;
        const unsigned* wb = (const unsigned*)&mwb;
        unsigned a0 = wa[wsel]   >> bsh;
        unsigned a1 = wa[wsel+1] >> bsh;
        unsigned c0 = wb[wsel]   >> bsh;
        unsigned c1 = wb[wsel+1] >> bsh;

        #pragma unroll
        for (int nt = 0; nt < 16; ++nt) {
            s0 += (((a0 >> (nt*2)) & 1) ? 0.f : ex2(sf[nt][0]))
                + (((a1 >> (nt*2)) & 1) ? 0.f : ex2(sf[nt][1]));
            s1 += (((c0 >> (nt*2)) & 1) ? 0.f : ex2(sf[nt][2]))
                + (((c1 >> (nt*2)) & 1) ? 0.f : ex2(sf[nt][3]));
        }

        CP_WAIT0;
        __syncthreads();
    }

    s0 += __shfl_xor_sync(0xffffffffu, s0, 1);
    s0 += __shfl_xor_sync(0xffffffffu, s0, 2);
    s1 += __shfl_xor_sync(0xffffffffu, s1, 1);
    s1 += __shfl_xor_sync(0xffffffffu, s1, 2);
    const float inv0 = 1.f / s0;
    const float inv1 = 1.f / s1;

    // ================= PASS B: N-halved, WAIT1 pipeline (R15 schedule) =================
    float of[8][4];
    #pragma unroll
    for (int nt = 0; nt < 8; ++nt) { of[nt][0]=0.f; of[nt][1]=0.f; of[nt][2]=0.f; of[nt][3]=0.f; }

    ld_tile128(sb + OFF_V,  vp, 0, t);   // group: V(0)
    CP_COMMIT;
    ld_tile128(sb + OFF_K0, kp, 0, t);   // group: K(0)
    CP_COMMIT; CP_WAIT0;
    __syncthreads();

    for (int kt = 0; kt < NT; ++kt) {
        const int kbase = kt * TK;
        unsigned kc = sb + ((kt & 1) ? OFF_K1 : OFF_K0);
        if (kt+1 < NT) { ld_tile128(sb + ((kt & 1) ? OFF_K0 : OFF_K1), kp, (kt+1)*TK, t); }
        CP_COMMIT;                        // group: K(kt+1)

        uint4 mwa = *(const uint4*)(mb0 + kt*4);
        uint4 mwb = *(const uint4*)(mb1 + kt*4);
        const unsigned* wa = (const unsigned*)&mwa;
        const unsigned* wb = (const unsigned*)&mwb;

        #pragma unroll
        for (int h2 = 0; h2 < 2; ++h2) {
            float sf[8][4];
            #pragma unroll
            for (int nt = 0; nt < 8; ++nt) { sf[nt][0]=0.f; sf[nt][1]=0.f; sf[nt][2]=0.f; sf[nt][3]=0.f; }

            #pragma unroll
            for (int ks = 0; ks < 4; ++ks) {
                #pragma unroll
                for (int nt2 = 0; nt2 < 4; ++nt2) {
                    unsigned b0,b1,b2,b3;
                    unsigned a = kc + sw128((h2*64 + nt2*16 + (lane & 7) + ((lane >> 4) << 3))*128
                                            + (ks*16 + ((lane >> 3) & 1)*8)*2);
                    ldsm_x4(a, b0, b1, b2, b3);
                    mma16816(sf[2*nt2],   qa[ks], b0, b1);
                    mma16816(sf[2*nt2+1], qa[ks], b2, b3);
                }
            }

            const int sh = bsh + h2*16;
            unsigned a0 = wa[wsel]   >> sh;
            unsigned a1 = wa[wsel+1] >> sh;
            unsigned c0 = wb[wsel]   >> sh;
            unsigned c1 = wb[wsel+1] >> sh;

            #pragma unroll
            for (int nt = 0; nt < 8; ++nt) {
                int col = kbase + h2*64 + nt*8 + qc;
                float w0 = ((a0 >> (nt*2)) & 1) ? 0.f : ex2(sf[nt][0]) * inv0;
                float w1 = ((a1 >> (nt*2)) & 1) ? 0.f : ex2(sf[nt][1]) * inv0;
                float w2 = ((c0 >> (nt*2)) & 1) ? 0.f : ex2(sf[nt][2]) * inv1;
                float w3 = ((c1 >> (nt*2)) & 1) ? 0.f : ex2(sf[nt][3]) * inv1;
                *(float2*)(wp + (size_t)row0*Sdim + col) = make_float2(w0, w1);
                *(float2*)(wp + (size_t)row1*Sdim + col) = make_float2(w2, w3);
                sf[nt][0]=w0; sf[nt][1]=w1; sf[nt][2]=w2; sf[nt][3]=w3;
            }

            unsigned pa[4][4];
            #pragma unroll
            for (int ks = 0; ks < 4; ++ks) {
                pa[ks][0] = pack_h2(sf[2*ks][0],   sf[2*ks][1]);
                pa[ks][1] = pack_h2(sf[2*ks][2],   sf[2*ks][3]);
                pa[ks][2] = pack_h2(sf[2*ks+1][0], sf[2*ks+1][1]);
                pa[ks][3] = pack_h2(sf[2*ks+1][2], sf[2*ks+1][3]);
            }

            if (h2 == 0) {
                CP_WAIT1;       // V(kt) complete; K(kt+1) stays in flight
                __syncthreads();
            }

            #pragma unroll
            for (int ks = 0; ks < 4; ++ks) {
                #pragma unroll
                for (int nt2 = 0; nt2 < 4; ++nt2) {
                    unsigned b0,b1,b2,b3;
                    unsigned a = sb + OFF_V + sw128((h2*64 + ks*16 + (lane & 7) + ((lane >> 3) & 1)*8)*128
                                                    + (nt2*16 + (lane >> 4)*8)*2);
                    ldsm_x4_t(a, b0, b1, b2, b3);
                    mma16816(of[2*nt2],   pa[ks], b0, b1);
                    mma16816(of[2*nt2+1], pa[ks], b2, b3);
                }
            }
        }

        CP_WAIT0;               // K(kt+1) complete for all threads
        __syncthreads();        // ...and visible block-wide; V buffer free
        if (kt+1 < NT) { ld_tile128(sb + OFF_V, vp, (kt+1)*TK, t); CP_COMMIT; }   // group: V(kt+1)
    }

    #pragma unroll
    for (int nt = 0; nt < 8; ++nt) {
        int col = nt*8 + qc;
        *(float2*)(op + (size_t)row0*Ddim + col) = make_float2(of[nt][0], of[nt][1]);
        *(float2*)(op + (size_t)row1*Ddim + col) = make_float2(of[nt][2], of[nt][3]);
    }
}

extern "C" void kernel_launch(void* const* d_in, const int* in_sizes, int n_in,
                              void* d_out, int out_size) {
    const float* q    = (const float*)d_in[0];
    const float* k    = (const float*)d_in[1];
    const float* v    = (const float*)d_in[2];
    const float* mask = (const float*)d_in[3];
    float* out = (float*)d_out;
    float* wgt = out + (size_t)Bdim*Hdim*Sdim*Ddim;

    prep_all<<<4096, 256>>>(q, k, v, mask);

    cudaFuncSetAttribute(attn_mma_kernel,
                         cudaFuncAttributeMaxDynamicSharedMemorySize, SMEM_BYTES);
    dim3 grid(Bdim*Hdim*(Sdim/TQ));
    attn_mma_kernel<<<grid, 128, SMEM_BYTES>>>(out, wgt);
}